// round 1
// baseline (speedup 1.0000x reference)
#include <cuda_runtime.h>

#define HH 512
#define WW 512
#define BB 8
#define TX 32
#define TY 16
#define SW (TX + 4)
#define SH (TY + 4)

// Scratch for per-pixel linear coefficients (a: 9 ch, b: 3 ch), channel-planar.
__device__ float g_scr_a[BB * 9 * HH * WW];
__device__ float g_scr_b[BB * 3 * HH * WW];

__device__ __forceinline__ int refl(int q, int n) {
    if (q < 0) q = -q;
    if (q >= n) q = 2 * n - 2 - q;
    return q;
}

// Stage 1: box-blur 21 product channels (direct 25-tap, sharing 6 smem reads
// per tap across all products), then per-pixel 3x3 symmetric solve.
__global__ __launch_bounds__(512)
void gf_stage1(const float* __restrict__ gd, const float* __restrict__ pd) {
    __shared__ float sm[6][SH][SW];
    const int b = blockIdx.z;
    const int x0 = blockIdx.x * TX, y0 = blockIdx.y * TY;
    const int tx = threadIdx.x, ty = threadIdx.y;
    const int tid = ty * TX + tx;

    // Cooperative load of 6 base channels with reflect padding.
    for (int i = tid; i < 6 * SH * SW; i += 512) {
        int ch = i / (SH * SW);
        int rem = i % (SH * SW);
        int r = rem / SW, c = rem % SW;
        int gy = refl(y0 + r - 2, HH);
        int gx = refl(x0 + c - 2, WW);
        float v;
        if (ch < 3) v = gd[((b * 3 + ch) * HH + gy) * WW + gx];
        else        v = pd[((b * 3 + (ch - 3)) * HH + gy) * WW + gx];
        sm[ch][r][c] = v;
    }
    __syncthreads();

    float sg0 = 0.f, sg1 = 0.f, sg2 = 0.f, sp0 = 0.f, sp1 = 0.f, sp2 = 0.f;
    float s00 = 0.f, s01 = 0.f, s02 = 0.f, s11 = 0.f, s12 = 0.f, s22 = 0.f;
    float q00 = 0.f, q01 = 0.f, q02 = 0.f;
    float q10 = 0.f, q11 = 0.f, q12 = 0.f;
    float q20 = 0.f, q21 = 0.f, q22 = 0.f;

#pragma unroll
    for (int dy = 0; dy < 5; dy++) {
#pragma unroll
        for (int dx = 0; dx < 5; dx++) {
            float g0 = sm[0][ty + dy][tx + dx];
            float g1 = sm[1][ty + dy][tx + dx];
            float g2 = sm[2][ty + dy][tx + dx];
            float p0 = sm[3][ty + dy][tx + dx];
            float p1 = sm[4][ty + dy][tx + dx];
            float p2 = sm[5][ty + dy][tx + dx];
            sg0 += g0; sg1 += g1; sg2 += g2;
            sp0 += p0; sp1 += p1; sp2 += p2;
            s00 += g0 * g0; s01 += g0 * g1; s02 += g0 * g2;
            s11 += g1 * g1; s12 += g1 * g2; s22 += g2 * g2;
            q00 += g0 * p0; q01 += g0 * p1; q02 += g0 * p2;
            q10 += g1 * p0; q11 += g1 * p1; q12 += g1 * p2;
            q20 += g2 * p0; q21 += g2 * p1; q22 += g2 * p2;
        }
    }

    const float inv = 1.0f / 25.0f;
    const float eps = 1e-4f;
    float mI0 = sg0 * inv, mI1 = sg1 * inv, mI2 = sg2 * inv;
    float mp0 = sp0 * inv, mp1 = sp1 * inv, mp2 = sp2 * inv;

    // A = var_I + eps*I (symmetric)
    float a00 = s00 * inv - mI0 * mI0 + eps;
    float a01 = s01 * inv - mI0 * mI1;
    float a02 = s02 * inv - mI0 * mI2;
    float a11 = s11 * inv - mI1 * mI1 + eps;
    float a12 = s12 * inv - mI1 * mI2;
    float a22 = s22 * inv - mI2 * mI2 + eps;

    // rhs[c][cp] = cov_Ip
    float c00 = q00 * inv - mI0 * mp0, c01 = q01 * inv - mI0 * mp1, c02 = q02 * inv - mI0 * mp2;
    float c10 = q10 * inv - mI1 * mp0, c11 = q11 * inv - mI1 * mp1, c12 = q12 * inv - mI1 * mp2;
    float c20 = q20 * inv - mI2 * mp0, c21 = q21 * inv - mI2 * mp1, c22 = q22 * inv - mI2 * mp2;

    // Inverse of symmetric 3x3 via adjugate.
    float i00 = a11 * a22 - a12 * a12;
    float i01 = a02 * a12 - a01 * a22;
    float i02 = a01 * a12 - a02 * a11;
    float i11 = a00 * a22 - a02 * a02;
    float i12 = a01 * a02 - a00 * a12;
    float i22 = a00 * a11 - a01 * a01;
    float det = a00 * i00 + a01 * i01 + a02 * i02;
    float rd = 1.0f / det;
    i00 *= rd; i01 *= rd; i02 *= rd; i11 *= rd; i12 *= rd; i22 *= rd;

    // a[c][cp] = invA[c][:] . rhs[:][cp]
    float A00 = i00 * c00 + i01 * c10 + i02 * c20;
    float A01 = i00 * c01 + i01 * c11 + i02 * c21;
    float A02 = i00 * c02 + i01 * c12 + i02 * c22;
    float A10 = i01 * c00 + i11 * c10 + i12 * c20;
    float A11 = i01 * c01 + i11 * c11 + i12 * c21;
    float A12 = i01 * c02 + i11 * c12 + i12 * c22;
    float A20 = i02 * c00 + i12 * c10 + i22 * c20;
    float A21 = i02 * c01 + i12 * c11 + i22 * c21;
    float A22 = i02 * c02 + i12 * c12 + i22 * c22;

    float b0 = mp0 - (A00 * mI0 + A10 * mI1 + A20 * mI2);
    float b1 = mp1 - (A01 * mI0 + A11 * mI1 + A21 * mI2);
    float b2 = mp2 - (A02 * mI0 + A12 * mI1 + A22 * mI2);

    const int y = y0 + ty, x = x0 + tx;
    const long long pofs = (long long)y * WW + x;
    float* ab = g_scr_a + (long long)b * 9 * HH * WW + pofs;
    ab[0 * HH * WW] = A00; ab[1 * HH * WW] = A01; ab[2 * HH * WW] = A02;
    ab[3 * HH * WW] = A10; ab[4 * HH * WW] = A11; ab[5 * HH * WW] = A12;
    ab[6 * HH * WW] = A20; ab[7 * HH * WW] = A21; ab[8 * HH * WW] = A22;
    float* bb = g_scr_b + (long long)b * 3 * HH * WW + pofs;
    bb[0 * HH * WW] = b0; bb[1 * HH * WW] = b1; bb[2 * HH * WW] = b2;
}

// Stage 2: separable box-blur of 12 channels (a:9, b:3) + final combine.
__global__ __launch_bounds__(512)
void gf_stage2(const float* __restrict__ gd, float* __restrict__ out) {
    __shared__ float sm[12][SH][SW];
    __shared__ float hs[SH][TX];
    const int b = blockIdx.z;
    const int x0 = blockIdx.x * TX, y0 = blockIdx.y * TY;
    const int tx = threadIdx.x, ty = threadIdx.y;
    const int tid = ty * TX + tx;

    const float* abase = g_scr_a + (long long)b * 9 * HH * WW;
    const float* bbase = g_scr_b + (long long)b * 3 * HH * WW;

    for (int i = tid; i < 12 * SH * SW; i += 512) {
        int ch = i / (SH * SW);
        int rem = i % (SH * SW);
        int r = rem / SW, c = rem % SW;
        int gy = refl(y0 + r - 2, HH);
        int gx = refl(x0 + c - 2, WW);
        float v;
        if (ch < 9) v = abase[((long long)ch * HH + gy) * WW + gx];
        else        v = bbase[((long long)(ch - 9) * HH + gy) * WW + gx];
        sm[ch][r][c] = v;
    }
    __syncthreads();

    float mean[12];
#pragma unroll
    for (int ch = 0; ch < 12; ch++) {
        // Horizontal 5-sum over the extended-row region (SH*TX entries).
        for (int i = tid; i < SH * TX; i += 512) {
            int r = i / TX, x = i % TX;
            hs[r][x] = sm[ch][r][x] + sm[ch][r][x + 1] + sm[ch][r][x + 2]
                     + sm[ch][r][x + 3] + sm[ch][r][x + 4];
        }
        __syncthreads();
        mean[ch] = hs[ty][tx] + hs[ty + 1][tx] + hs[ty + 2][tx]
                 + hs[ty + 3][tx] + hs[ty + 4][tx];
        __syncthreads();
    }

    const int y = y0 + ty, x = x0 + tx;
    const long long pofs = (long long)y * WW + x;
    const float g0 = gd[((long long)(b * 3 + 0) * HH) * WW + pofs];
    const float g1 = gd[((long long)(b * 3 + 1) * HH) * WW + pofs];
    const float g2 = gd[((long long)(b * 3 + 2) * HH) * WW + pofs];

    const float inv = 1.0f / 25.0f;
#pragma unroll
    for (int cp = 0; cp < 3; cp++) {
        float o = g0 * mean[0 + cp] + g1 * mean[3 + cp] + g2 * mean[6 + cp] + mean[9 + cp];
        out[((long long)(b * 3 + cp) * HH) * WW + pofs] = o * inv;
    }
}

extern "C" void kernel_launch(void* const* d_in, const int* in_sizes, int n_in,
                              void* d_out, int out_size) {
    const float* gd = (const float*)d_in[0];
    const float* pd = (const float*)d_in[1];
    float* out = (float*)d_out;
    dim3 grid(WW / TX, HH / TY, BB);
    dim3 blk(TX, TY);
    gf_stage1<<<grid, blk>>>(gd, pd);
    gf_stage2<<<grid, blk>>>(gd, out);
}

// round 2
// speedup vs baseline: 1.4690x; 1.4690x over previous
#include <cuda_runtime.h>

#define HH 512
#define WW 512
#define BB 8
#define TX 32
#define TY 8
#define SW 36   // TX + 4
#define SH 12   // TY + 4
#define PLANE (HH * WW)

// Per-pixel linear coefficients, pixel-major, 3 float4 per pixel:
// f4_0={A00,A01,A02,A10} f4_1={A11,A12,A20,A21} f4_2={A22,b0,b1,b2}
__device__ float4 g_scr[BB * HH * WW * 3];

__device__ __forceinline__ int refl(int q, int n) {
    if (q < 0) q = -q;
    if (q >= n) q = 2 * n - 2 - q;
    return q;
}

__device__ __forceinline__ float4 f4add(float4 a, float4 b) {
    return make_float4(a.x + b.x, a.y + b.y, a.z + b.z, a.w + b.w);
}

// ---------------- Stage 1: separable product blur + 3x3 solve ----------------
__global__ __launch_bounds__(256, 3)
void gf_stage1(const float* __restrict__ gd, const float* __restrict__ pd) {
    __shared__ float sin[6][SH][SW];
    __shared__ float vs[21][TY][SW + 1];

    const int b = blockIdx.z;
    const int x0 = blockIdx.x * TX, y0 = blockIdx.y * TY;
    const int tx = threadIdx.x, ty = threadIdx.y;

    // --- cooperative load of 6 base channels, reflect computed once per pos ---
    const int bbase = b * 3 * PLANE;
#pragma unroll
    for (int rr = 0; rr < 2; rr++) {
        const int r = ty + rr * TY;
        if (r < SH) {
            const int gy = refl(y0 + r - 2, HH);
#pragma unroll
            for (int cc = 0; cc < 2; cc++) {
                const int c = tx + cc * TX;
                if (c < SW) {
                    const int gx = refl(x0 + c - 2, WW);
                    const int o = bbase + gy * WW + gx;
#pragma unroll
                    for (int ch = 0; ch < 3; ch++) {
                        sin[ch][r][c]     = gd[o + ch * PLANE];
                        sin[3 + ch][r][c] = pd[o + ch * PLANE];
                    }
                }
            }
        }
    }
    __syncthreads();

    // --- vertical 5-tap sums of 21 product channels ---
#pragma unroll
    for (int cc = 0; cc < 2; cc++) {
        const int c = tx + cc * TX;
        if (c < SW) {
            float a[21];
#pragma unroll
            for (int i = 0; i < 21; i++) a[i] = 0.f;
#pragma unroll
            for (int dy = 0; dy < 5; dy++) {
                const float g0 = sin[0][ty + dy][c];
                const float g1 = sin[1][ty + dy][c];
                const float g2 = sin[2][ty + dy][c];
                const float p0 = sin[3][ty + dy][c];
                const float p1 = sin[4][ty + dy][c];
                const float p2 = sin[5][ty + dy][c];
                a[0] += g0; a[1] += g1; a[2] += g2;
                a[3] += p0; a[4] += p1; a[5] += p2;
                a[6]  += g0 * g0; a[7]  += g0 * g1; a[8]  += g0 * g2;
                a[9]  += g1 * g1; a[10] += g1 * g2; a[11] += g2 * g2;
                a[12] += g0 * p0; a[13] += g0 * p1; a[14] += g0 * p2;
                a[15] += g1 * p0; a[16] += g1 * p1; a[17] += g1 * p2;
                a[18] += g2 * p0; a[19] += g2 * p1; a[20] += g2 * p2;
            }
#pragma unroll
            for (int i = 0; i < 21; i++) vs[i][ty][c] = a[i];
        }
    }
    __syncthreads();

    // --- horizontal 5-tap + per-pixel symmetric 3x3 solve ---
    float m[21];
#pragma unroll
    for (int i = 0; i < 21; i++)
        m[i] = vs[i][ty][tx] + vs[i][ty][tx + 1] + vs[i][ty][tx + 2]
             + vs[i][ty][tx + 3] + vs[i][ty][tx + 4];

    const float inv = 1.0f / 25.0f;
    const float eps = 1e-4f;
    const float mI0 = m[0] * inv, mI1 = m[1] * inv, mI2 = m[2] * inv;
    const float mp0 = m[3] * inv, mp1 = m[4] * inv, mp2 = m[5] * inv;

    const float a00 = m[6]  * inv - mI0 * mI0 + eps;
    const float a01 = m[7]  * inv - mI0 * mI1;
    const float a02 = m[8]  * inv - mI0 * mI2;
    const float a11 = m[9]  * inv - mI1 * mI1 + eps;
    const float a12 = m[10] * inv - mI1 * mI2;
    const float a22 = m[11] * inv - mI2 * mI2 + eps;

    const float c00 = m[12] * inv - mI0 * mp0, c01 = m[13] * inv - mI0 * mp1, c02 = m[14] * inv - mI0 * mp2;
    const float c10 = m[15] * inv - mI1 * mp0, c11 = m[16] * inv - mI1 * mp1, c12 = m[17] * inv - mI1 * mp2;
    const float c20 = m[18] * inv - mI2 * mp0, c21 = m[19] * inv - mI2 * mp1, c22 = m[20] * inv - mI2 * mp2;

    float i00 = a11 * a22 - a12 * a12;
    float i01 = a02 * a12 - a01 * a22;
    float i02 = a01 * a12 - a02 * a11;
    float i11 = a00 * a22 - a02 * a02;
    float i12 = a01 * a02 - a00 * a12;
    float i22 = a00 * a11 - a01 * a01;
    const float det = a00 * i00 + a01 * i01 + a02 * i02;
    const float rd = 1.0f / det;
    i00 *= rd; i01 *= rd; i02 *= rd; i11 *= rd; i12 *= rd; i22 *= rd;

    const float A00 = i00 * c00 + i01 * c10 + i02 * c20;
    const float A01 = i00 * c01 + i01 * c11 + i02 * c21;
    const float A02 = i00 * c02 + i01 * c12 + i02 * c22;
    const float A10 = i01 * c00 + i11 * c10 + i12 * c20;
    const float A11 = i01 * c01 + i11 * c11 + i12 * c21;
    const float A12 = i01 * c02 + i11 * c12 + i12 * c22;
    const float A20 = i02 * c00 + i12 * c10 + i22 * c20;
    const float A21 = i02 * c01 + i12 * c11 + i22 * c21;
    const float A22 = i02 * c02 + i12 * c12 + i22 * c22;

    const float b0 = mp0 - (A00 * mI0 + A10 * mI1 + A20 * mI2);
    const float b1 = mp1 - (A01 * mI0 + A11 * mI1 + A21 * mI2);
    const float b2 = mp2 - (A02 * mI0 + A12 * mI1 + A22 * mI2);

    const int pix = (b * HH + (y0 + ty)) * WW + (x0 + tx);
    float4* dst = g_scr + pix * 3;
    dst[0] = make_float4(A00, A01, A02, A10);
    dst[1] = make_float4(A11, A12, A20, A21);
    dst[2] = make_float4(A22, b0, b1, b2);
}

// ---------------- Stage 2: separable blur of 3 float4 channels + combine ----------------
__global__ __launch_bounds__(256)
void gf_stage2(const float* __restrict__ gd, float* __restrict__ out) {
    __shared__ float4 sin4[3][SH][SW];
    __shared__ float4 vs4[3][TY][SW + 1];

    const int b = blockIdx.z;
    const int x0 = blockIdx.x * TX, y0 = blockIdx.y * TY;
    const int tx = threadIdx.x, ty = threadIdx.y;

    // --- cooperative load of the 3-float4-channel coefficient field ---
#pragma unroll
    for (int rr = 0; rr < 2; rr++) {
        const int r = ty + rr * TY;
        if (r < SH) {
            const int gy = refl(y0 + r - 2, HH);
#pragma unroll
            for (int cc = 0; cc < 2; cc++) {
                const int c = tx + cc * TX;
                if (c < SW) {
                    const int gx = refl(x0 + c - 2, WW);
                    const int pix = (b * HH + gy) * WW + gx;
                    const float4* src = g_scr + pix * 3;
#pragma unroll
                    for (int ch = 0; ch < 3; ch++)
                        sin4[ch][r][c] = src[ch];
                }
            }
        }
    }
    __syncthreads();

    // --- vertical 5-tap sums ---
#pragma unroll
    for (int cc = 0; cc < 2; cc++) {
        const int c = tx + cc * TX;
        if (c < SW) {
#pragma unroll
            for (int ch = 0; ch < 3; ch++) {
                float4 s = sin4[ch][ty][c];
                s = f4add(s, sin4[ch][ty + 1][c]);
                s = f4add(s, sin4[ch][ty + 2][c]);
                s = f4add(s, sin4[ch][ty + 3][c]);
                s = f4add(s, sin4[ch][ty + 4][c]);
                vs4[ch][ty][c] = s;
            }
        }
    }
    __syncthreads();

    // --- horizontal 5-tap + combine with guidance ---
    float4 m0 = vs4[0][ty][tx];
    m0 = f4add(m0, vs4[0][ty][tx + 1]); m0 = f4add(m0, vs4[0][ty][tx + 2]);
    m0 = f4add(m0, vs4[0][ty][tx + 3]); m0 = f4add(m0, vs4[0][ty][tx + 4]);
    float4 m1 = vs4[1][ty][tx];
    m1 = f4add(m1, vs4[1][ty][tx + 1]); m1 = f4add(m1, vs4[1][ty][tx + 2]);
    m1 = f4add(m1, vs4[1][ty][tx + 3]); m1 = f4add(m1, vs4[1][ty][tx + 4]);
    float4 m2 = vs4[2][ty][tx];
    m2 = f4add(m2, vs4[2][ty][tx + 1]); m2 = f4add(m2, vs4[2][ty][tx + 2]);
    m2 = f4add(m2, vs4[2][ty][tx + 3]); m2 = f4add(m2, vs4[2][ty][tx + 4]);

    const int o = (b * 3 * HH + (y0 + ty)) * WW + (x0 + tx);
    const float g0 = gd[o];
    const float g1 = gd[o + PLANE];
    const float g2 = gd[o + 2 * PLANE];

    const float inv = 1.0f / 25.0f;
    out[o]             = (g0 * m0.x + g1 * m0.w + g2 * m1.z + m2.y) * inv;
    out[o + PLANE]     = (g0 * m0.y + g1 * m1.x + g2 * m1.w + m2.z) * inv;
    out[o + 2 * PLANE] = (g0 * m0.z + g1 * m1.y + g2 * m2.x + m2.w) * inv;
}

extern "C" void kernel_launch(void* const* d_in, const int* in_sizes, int n_in,
                              void* d_out, int out_size) {
    const float* gd = (const float*)d_in[0];
    const float* pd = (const float*)d_in[1];
    float* out = (float*)d_out;
    dim3 grid(WW / TX, HH / TY, BB);
    dim3 blk(TX, TY);
    gf_stage1<<<grid, blk>>>(gd, pd);
    gf_stage2<<<grid, blk>>>(gd, out);
}